// round 15
// baseline (speedup 1.0000x reference)
#include <cuda_runtime.h>
#include <cuda_fp16.h>
#include <math.h>
#include <stdint.h>

#define BB 4
#define SS 2048
#define DD 1024
#define HH 16
#define DH 64
#define M_TOT (BB*SS)   // 8192
#define KK 1024

// ---- GEMM tiling (fp16, 512 thr, 2 CTAs/SM, warp tile 32x32) ----
#define BM 128
#define BN 128
#define BKH 64                    // k-chunk in halfs
#define NCH (KK/BKH)              // 16
#define PITH 72                   // smem row pitch (halfs) = 144B
#define A_STH (BM*PITH)           // 9216 halfs
#define B_STH (BN*PITH)           // 9216 halfs
#define STGH (A_STH+B_STH)        // 18432 halfs
#define GEMM_SMEM (3*STGH*2)      // 110592 bytes

// ---- scratch (allocation-free rule: __device__ globals) ----
__device__ __half g_q[BB*HH*SS*DH];
__device__ __half g_k[BB*HH*SS*DH];
__device__ __half g_v[BB*HH*SS*DH];
__device__ __half g_att[(size_t)M_TOT*DD];
__device__ __half g_xr[(size_t)M_TOT*DD];      // fp16 x
__device__ __half g_wir[(size_t)3*DD*DD];      // fp16 in_proj_w
__device__ __half g_wor[(size_t)DD*DD];        // fp16 out_proj_w

// ---------------- helpers ----------------
__device__ __forceinline__ float ex2(float x) {
    float y;
    asm("ex2.approx.f32 %0, %1;" : "=f"(y) : "f"(x));
    return y;
}
__device__ __forceinline__ void mma_h(float* d, const uint32_t* a, const uint32_t* b) {
    asm volatile(
        "mma.sync.aligned.m16n8k16.row.col.f32.f16.f16.f32 "
        "{%0,%1,%2,%3}, {%4,%5,%6,%7}, {%8,%9}, {%0,%1,%2,%3};"
        : "+f"(d[0]), "+f"(d[1]), "+f"(d[2]), "+f"(d[3])
        : "r"(a[0]), "r"(a[1]), "r"(a[2]), "r"(a[3]), "r"(b[0]), "r"(b[1]));
}
__device__ __forceinline__ void ldsm4(uint32_t addr, uint32_t* d) {
    asm volatile("ldmatrix.sync.aligned.m8n8.x4.shared.b16 {%0,%1,%2,%3}, [%4];"
        : "=r"(d[0]), "=r"(d[1]), "=r"(d[2]), "=r"(d[3]) : "r"(addr));
}
__device__ __forceinline__ void ldsm4t(uint32_t addr, uint32_t* d) {
    asm volatile("ldmatrix.sync.aligned.m8n8.x4.trans.shared.b16 {%0,%1,%2,%3}, [%4];"
        : "=r"(d[0]), "=r"(d[1]), "=r"(d[2]), "=r"(d[3]) : "r"(addr));
}
__device__ __forceinline__ uint32_t smem_u32(const void* p) {
    uint32_t a;
    asm("{ .reg .u64 t; cvta.to.shared.u64 t, %1; cvt.u32.u64 %0, t; }"
        : "=r"(a) : "l"(p));
    return a;
}
__device__ __forceinline__ void cp16(uint32_t dst, const void* src) {
    asm volatile("cp.async.cg.shared.global [%0], [%1], 16;"
                 :: "r"(dst), "l"(src) : "memory");
}
__device__ __forceinline__ void cp_commit() {
    asm volatile("cp.async.commit_group;" ::: "memory");
}
template<int N> __device__ __forceinline__ void cp_wait() {
    asm volatile("cp.async.wait_group %0;" :: "n"(N) : "memory");
}
__device__ __forceinline__ uint32_t h2pack(float a, float b) {
    __half2 h = __floats2half2_rn(a, b);
    return *(uint32_t*)&h;
}

// ---------------------------------------------------------------------------
// pre-convert: fp32 -> fp16 (rn), all three inputs in one launch
// ---------------------------------------------------------------------------
#define N4_X   (M_TOT*DD/4)
#define N4_WI  (3*DD*DD/4)
#define N4_WO  (DD*DD/4)
__global__ __launch_bounds__(256)
void roundcpy_all(const float4* __restrict__ x,  uint2* __restrict__ dx,
                  const float4* __restrict__ wi, uint2* __restrict__ dwi,
                  const float4* __restrict__ wo, uint2* __restrict__ dwo)
{
    int i = blockIdx.x * 256 + threadIdx.x;
    const float4* s;
    uint2* d;
    int off;
    if (i < N4_X)              { s = x;  d = dx;  off = i; }
    else if (i < N4_X + N4_WI) { s = wi; d = dwi; off = i - N4_X; }
    else                       { s = wo; d = dwo; off = i - N4_X - N4_WI; }
    float4 v = s[off];
    __half2 a = __floats2half2_rn(v.x, v.y);
    __half2 b = __floats2half2_rn(v.z, v.w);
    uint2 u;
    u.x = *(uint32_t*)&a;
    u.y = *(uint32_t*)&b;
    d[off] = u;
}

// ---------------------------------------------------------------------------
// fp16 mma.sync GEMM (unchanged from round 13/14 — passed): 512 threads,
// 16 warps 4m x 4n (warp 32x32), 2 CTAs/SM, BK=64, 3-stage cp.async.
// ---------------------------------------------------------------------------
__global__ __launch_bounds__(512, 2)
void gemm_tc(const __half* __restrict__ A, const __half* __restrict__ W,
             const float* __restrict__ bias, float* __restrict__ Cout, int mode)
{
    extern __shared__ __half smh[];
    const uint32_t sb = smem_u32(smh);

    const int tid  = threadIdx.x;
    const int wid  = tid >> 5;
    const int lane = tid & 31;
    const int gid  = lane >> 2;
    const int tig  = lane & 3;
    const int wm   = (wid >> 2) * 32;
    const int wn   = (wid & 3) * 32;
    const int m0   = blockIdx.y * BM;
    const int n0   = blockIdx.x * BN;

    const int ar = tid >> 2;
    const int ac = (tid & 3) * 16;
    const __half* gA = A + (size_t)(m0 + ar) * KK + ac;
    const __half* gB = W + (size_t)(n0 + ar) * KK + ac;
    const uint32_t sA_cp = sb + (uint32_t)(ar * PITH + ac) * 2;
    const uint32_t sB_cp = sb + (uint32_t)(A_STH + ar * PITH + ac) * 2;

    const uint32_t aoff = (uint32_t)((wm + (lane & 15)) * PITH + ((lane >> 1) & 8)) * 2;
    const uint32_t boff = (uint32_t)(A_STH + (wn + (lane & 7) + ((lane >> 1) & 8)) * PITH
                                     + (lane & 8)) * 2;

#define LOADCHUNK(c, s) do {                                        \
        uint32_t off_ = (uint32_t)(s) * (STGH * 2);                 \
        const __half* pa_ = gA + (c) * BKH;                         \
        const __half* pb_ = gB + (c) * BKH;                         \
        cp16(sA_cp + off_ +  0, pa_ + 0);                           \
        cp16(sA_cp + off_ + 16, pa_ + 8);                           \
        cp16(sB_cp + off_ +  0, pb_ + 0);                           \
        cp16(sB_cp + off_ + 16, pb_ + 8);                           \
    } while (0)

    LOADCHUNK(0, 0); cp_commit();
    LOADCHUNK(1, 1); cp_commit();

    float acc[2][4][4];
#pragma unroll
    for (int mi = 0; mi < 2; mi++)
#pragma unroll
        for (int ni = 0; ni < 4; ni++)
#pragma unroll
            for (int e = 0; e < 4; e++) acc[mi][ni][e] = 0.f;

    int s = 0;
    for (int c = 0; c < NCH; c++) {
        cp_wait<1>();
        __syncthreads();

        if (c + 2 < NCH) {
            int s2 = s + 2; if (s2 >= 3) s2 -= 3;
            LOADCHUNK(c + 2, s2);
        }
        cp_commit();

        const uint32_t stg = sb + (uint32_t)s * (STGH * 2);
#pragma unroll
        for (int kb = 0; kb < 4; kb++) {
            uint32_t af[2][4], bf[2][4];
#pragma unroll
            for (int mi = 0; mi < 2; mi++)
                ldsm4(stg + aoff + mi * (16 * PITH * 2) + kb * 32, af[mi]);
#pragma unroll
            for (int nj = 0; nj < 2; nj++)
                ldsm4(stg + boff + nj * (16 * PITH * 2) + kb * 32, bf[nj]);
#pragma unroll
            for (int njp = 0; njp < 2; njp++) {
#pragma unroll
                for (int mi = 0; mi < 2; mi++) {
                    mma_h(acc[mi][2 * njp],     af[mi], bf[njp]);
                    mma_h(acc[mi][2 * njp + 1], af[mi], bf[njp] + 2);
                }
            }
        }
        if (++s == 3) s = 0;
    }
#undef LOADCHUNK

#pragma unroll
    for (int ni = 0; ni < 4; ni++) {
        const int n = n0 + wn + ni * 8 + 2 * tig;
        const float b0 = __ldg(bias + n);
        const float b1 = __ldg(bias + n + 1);

        if (mode == 0) {
            const int chunk = n >> 10;
            const int cm = n & 1023;
            const int h  = cm >> 6;
            const int dd = cm & 63;
            __half* dst = (chunk == 0) ? g_q : (chunk == 1) ? g_k : g_v;
#pragma unroll
            for (int mi = 0; mi < 2; mi++) {
                const int r0 = m0 + wm + mi * 16 + gid;
                const int bb0 = r0 >> 11, sr0 = r0 & 2047;
                const int r1 = r0 + 8;
                const int bb1 = r1 >> 11, sr1 = r1 & 2047;
                __half2 v0 = __floats2half2_rn(acc[mi][ni][0] + b0, acc[mi][ni][1] + b1);
                __half2 v1 = __floats2half2_rn(acc[mi][ni][2] + b0, acc[mi][ni][3] + b1);
                *(__half2*)(dst + ((size_t)(bb0 * HH + h) * SS + sr0) * DH + dd) = v0;
                *(__half2*)(dst + ((size_t)(bb1 * HH + h) * SS + sr1) * DH + dd) = v1;
            }
        } else {
#pragma unroll
            for (int mi = 0; mi < 2; mi++) {
                const int r0 = m0 + wm + mi * 16 + gid;
                const int r1 = r0 + 8;
                float2 v0 = make_float2(acc[mi][ni][0] + b0, acc[mi][ni][1] + b1);
                float2 v1 = make_float2(acc[mi][ni][2] + b0, acc[mi][ni][3] + b1);
                *(float2*)(Cout + (size_t)r0 * DD + n) = v0;
                *(float2*)(Cout + (size_t)r1 * DD + n) = v1;
            }
        }
    }
}

// ---------------------------------------------------------------------------
// fp16 flash attention — register-P, 3 CTAs/SM.
// kv-tile processed in two 32-t halves (QK(half) -> exp -> PV(half)) so the
// live S fragment is p[4][4] (16 regs) -> total ~79 regs -> fits the
// 80-reg/3-CTA budget. Arithmetic order identical to round 14 (bitwise).
// q-tile 128, kv-tile 64. One __syncthreads per iteration, 3-stage K/V.
// smem (halfs): [Q 128x72 (prologue only)][K 3x64x72][V 3x64x72] = 73728 B
// ---------------------------------------------------------------------------
#define QP_H   9216
#define K_OFFH QP_H                    // 9216
#define KBUFH  4608                    // 64*72
#define V_OFFH (K_OFFH + 3*KBUFH)      // 23040
#define VBUFH  4608
#define ATT_SMEM ((V_OFFH + 3*VBUFH)*2)   // 73728 bytes

__global__ __launch_bounds__(256, 3)
void attn_tc()
{
    extern __shared__ __half smh[];

    const int tid  = threadIdx.x;
    const int wid  = tid >> 5;
    const int lane = tid & 31;
    const int g    = lane >> 2;
    const int tig  = lane & 3;
    const int wq   = wid * 16;
    const int q0   = blockIdx.x * 128;
    const int bh   = blockIdx.y;

    const __half* gq = g_q + (size_t)bh * SS * DH;
    const __half* gk = g_k + (size_t)bh * SS * DH;
    const __half* gv = g_v + (size_t)bh * SS * DH;

    const uint32_t sQ = smem_u32(smh);
    const uint32_t sK = sQ + K_OFFH * 2;
    const uint32_t sV = sQ + V_OFFH * 2;

    // ---- prologue: Q + KV tiles 0,1 ----
#pragma unroll
    for (int j = 0; j < 4; j++) {
        int ch = tid + j * 256;
        int r = ch >> 3, c = ch & 7;
        cp16(sQ + (uint32_t)(r * PITH + c * 8) * 2, gq + (size_t)(q0 + r) * DH + c * 8);
    }
#pragma unroll
    for (int j = 0; j < 2; j++) {
        int ch = tid + j * 256;
        int t = ch >> 3, c = ch & 7;
        cp16(sK + (uint32_t)(t * PITH + c * 8) * 2, gk + (size_t)t * DH + c * 8);
        cp16(sV + (uint32_t)(t * PITH + c * 8) * 2, gv + (size_t)t * DH + c * 8);
    }
    cp_commit();
#pragma unroll
    for (int j = 0; j < 2; j++) {
        int ch = tid + j * 256;
        int t = ch >> 3, c = ch & 7;
        cp16(sK + (uint32_t)(KBUFH + t * PITH + c * 8) * 2, gk + (size_t)(64 + t) * DH + c * 8);
        cp16(sV + (uint32_t)(VBUFH + t * PITH + c * 8) * 2, gv + (size_t)(64 + t) * DH + c * 8);
    }
    cp_commit();

    cp_wait<1>();
    __syncthreads();

    // ---- Q A-fragments (16 q rows, k16 x 4), loaded once ----
    const uint32_t q_ab = sQ + (uint32_t)((lane & 15) * PITH + ((lane >> 1) & 8)) * 2;
    uint32_t qa[4][4];
#pragma unroll
    for (int kb = 0; kb < 4; kb++)
        ldsm4(q_ab + (uint32_t)((wq * PITH + kb * 16) * 2), qa[kb]);

    const uint32_t k_bb = sK + (uint32_t)(((lane & 7) + ((lane >> 1) & 8)) * PITH + (lane & 8)) * 2;
    const uint32_t v_bb = sV + (uint32_t)((lane & 15) * PITH + ((lane >> 1) & 8)) * 2;

    float oacc[8][4];
#pragma unroll
    for (int nj = 0; nj < 8; nj++)
#pragma unroll
        for (int e = 0; e < 4; e++) oacc[nj][e] = 0.f;
    float lp[2] = {0.f, 0.f};

    const float CEXP = 0.18033688011112042f;   // log2(e)/8

    int s = 0;
    for (int i = 0; i < SS / 64; i++) {
        cp_wait<1>();
        __syncthreads();           // tile i visible to all warps

        const uint32_t kstage = k_bb + (uint32_t)(s * KBUFH) * 2;
        const uint32_t vstage = v_bb + (uint32_t)(s * VBUFH) * 2;

#pragma unroll
        for (int half = 0; half < 2; half++) {
            // ---- QK^T: S[16 q x 32 t] for this t-half ----
            float p[4][4];
#pragma unroll
            for (int nj = 0; nj < 4; nj++)
#pragma unroll
                for (int e = 0; e < 4; e++) p[nj][e] = 0.f;

#pragma unroll
            for (int kb = 0; kb < 4; kb++) {
#pragma unroll
                for (int njp = 0; njp < 2; njp++) {
                    uint32_t bfr[4];
                    ldsm4(kstage + (uint32_t)(((half * 32 + njp * 16) * PITH + kb * 16) * 2), bfr);
                    mma_h(p[2 * njp],     qa[kb], bfr);
                    mma_h(p[2 * njp + 1], qa[kb], bfr + 2);
                }
            }

            // ---- softmax (no max subtraction), in registers ----
#pragma unroll
            for (int nj = 0; nj < 4; nj++) {
                p[nj][0] = ex2(p[nj][0] * CEXP);
                p[nj][1] = ex2(p[nj][1] * CEXP);
                p[nj][2] = ex2(p[nj][2] * CEXP);
                p[nj][3] = ex2(p[nj][3] * CEXP);
                lp[0] += p[nj][0] + p[nj][1];
                lp[1] += p[nj][2] + p[nj][3];
            }

            // ---- P @ V for this t-half (t-blocks kbl within half) ----
#pragma unroll
            for (int kbl = 0; kbl < 2; kbl++) {
                const int kb = half * 2 + kbl;     // global 16-t block
                uint32_t pa[4];
                pa[0] = h2pack(p[2 * kbl][0],     p[2 * kbl][1]);
                pa[1] = h2pack(p[2 * kbl][2],     p[2 * kbl][3]);
                pa[2] = h2pack(p[2 * kbl + 1][0], p[2 * kbl + 1][1]);
                pa[3] = h2pack(p[2 * kbl + 1][2], p[2 * kbl + 1][3]);
#pragma unroll
                for (int njp = 0; njp < 4; njp++) {
                    uint32_t vf[4];
                    ldsm4t(vstage + (uint32_t)((kb * 16 * PITH + njp * 16) * 2), vf);
                    mma_h(oacc[2 * njp],     pa, vf);
                    mma_h(oacc[2 * njp + 1], pa, vf + 2);
                }
            }
        }

        // ---- prefetch tile i+2 into stage (s+2)%3 (no barrier needed) ----
        if (i + 2 < SS / 64) {
            int sp = s + 2; if (sp >= 3) sp -= 3;
            const size_t t0 = (size_t)(i + 2) * 64;
#pragma unroll
            for (int j = 0; j < 2; j++) {
                int ch = tid + j * 256;
                int t = ch >> 3, c = ch & 7;
                cp16(sK + (uint32_t)(sp * KBUFH + t * PITH + c * 8) * 2,
                     gk + (t0 + t) * DH + c * 8);
                cp16(sV + (uint32_t)(sp * VBUFH + t * PITH + c * 8) * 2,
                     gv + (t0 + t) * DH + c * 8);
            }
        }
        cp_commit();
        if (++s == 3) s = 0;
    }

    // ---- normalize and write fp16 g_att [B,S,D] ----
    float ri[2];
#pragma unroll
    for (int hh = 0; hh < 2; hh++) {
        float l = lp[hh];
        l += __shfl_xor_sync(0xffffffffu, l, 1);
        l += __shfl_xor_sync(0xffffffffu, l, 2);
        ri[hh] = 1.f / l;
    }

    const int bb = bh >> 4;
    const int h  = bh & 15;
    const int r0 = q0 + wq + g;
    __half* base = g_att + ((size_t)bb * SS + r0) * DD + h * DH + 2 * tig;
#pragma unroll
    for (int nj = 0; nj < 8; nj++) {
        __half2 v0 = __floats2half2_rn(oacc[nj][0] * ri[0],
                                       oacc[nj][1] * ri[0]);
        __half2 v1 = __floats2half2_rn(oacc[nj][2] * ri[1],
                                       oacc[nj][3] * ri[1]);
        *(__half2*)(base + nj * 8) = v0;
        *(__half2*)(base + (size_t)8 * DD + nj * 8) = v1;
    }
}

// ---------------------------------------------------------------------------

extern "C" void kernel_launch(void* const* d_in, const int* in_sizes, int n_in,
                              void* d_out, int out_size)
{
    const float* x      = (const float*)d_in[0];
    const float* w_in   = (const float*)d_in[1];
    const float* b_in   = (const float*)d_in[2];
    const float* w_out  = (const float*)d_in[3];
    const float* b_out  = (const float*)d_in[4];
    float* out = (float*)d_out;

    (void)in_sizes; (void)n_in; (void)out_size;

    cudaFuncSetAttribute(gemm_tc, cudaFuncAttributeMaxDynamicSharedMemorySize,
                         GEMM_SMEM);
    cudaFuncSetAttribute(attn_tc, cudaFuncAttributeMaxDynamicSharedMemorySize,
                         ATT_SMEM);

    __half *xr, *wir, *wor, *attp;
    cudaGetSymbolAddress((void**)&xr,   g_xr);
    cudaGetSymbolAddress((void**)&wir,  g_wir);
    cudaGetSymbolAddress((void**)&wor,  g_wor);
    cudaGetSymbolAddress((void**)&attp, g_att);

    // 0) pre-convert all inputs to fp16 (single launch)
    roundcpy_all<<<(N4_X + N4_WI + N4_WO) / 256, 256>>>(
        (const float4*)x,     (uint2*)xr,
        (const float4*)w_in,  (uint2*)wir,
        (const float4*)w_out, (uint2*)wor);

    // 1) QKV projection (fp16 mma, 512 thr, 2 CTA/SM) + bias + head reshape
    gemm_tc<<<dim3(3 * DD / BN, M_TOT / BM), 512, GEMM_SMEM>>>(xr, wir, b_in, nullptr, 0);

    // 2) fp16 flash attention, register-P, 3 CTA/SM, halved S live-range
    attn_tc<<<dim3(SS / 128, BB * HH), 256, ATT_SMEM>>>();

    // 3) out projection (fp16 mma, 512 thr, 2 CTA/SM) + bias -> fp32 out
    gemm_tc<<<dim3(DD / BN, M_TOT / BM), 512, GEMM_SMEM>>>(attp, wor, b_out, out, 1);
}

// round 16
// speedup vs baseline: 1.0220x; 1.0220x over previous
#include <cuda_runtime.h>
#include <cuda_fp16.h>
#include <math.h>
#include <stdint.h>

#define BB 4
#define SS 2048
#define DD 1024
#define HH 16
#define DH 64
#define M_TOT (BB*SS)   // 8192
#define KK 1024

// ---- GEMM tiling (fp16, 512 thr, 2 CTAs/SM, warp tile 32x32) ----
#define BM 128
#define BN 128
#define BKH 64                    // k-chunk in halfs
#define NCH (KK/BKH)              // 16
#define PITH 72                   // smem row pitch (halfs) = 144B
#define A_STH (BM*PITH)           // 9216 halfs
#define B_STH (BN*PITH)           // 9216 halfs
#define STGH (A_STH+B_STH)        // 18432 halfs
#define GEMM_SMEM (3*STGH*2)      // 110592 bytes

// ---- scratch (allocation-free rule: __device__ globals) ----
__device__ __half g_q[BB*HH*SS*DH];
__device__ __half g_k[BB*HH*SS*DH];
__device__ __half g_v[BB*HH*SS*DH];
__device__ __half g_att[(size_t)M_TOT*DD];
__device__ __half g_xr[(size_t)M_TOT*DD];      // fp16 x
__device__ __half g_wir[(size_t)3*DD*DD];      // fp16 in_proj_w
__device__ __half g_wor[(size_t)DD*DD];        // fp16 out_proj_w

// ---------------- helpers ----------------
__device__ __forceinline__ float ex2(float x) {
    float y;
    asm("ex2.approx.f32 %0, %1;" : "=f"(y) : "f"(x));
    return y;
}
__device__ __forceinline__ void mma_h(float* d, const uint32_t* a, const uint32_t* b) {
    asm volatile(
        "mma.sync.aligned.m16n8k16.row.col.f32.f16.f16.f32 "
        "{%0,%1,%2,%3}, {%4,%5,%6,%7}, {%8,%9}, {%0,%1,%2,%3};"
        : "+f"(d[0]), "+f"(d[1]), "+f"(d[2]), "+f"(d[3])
        : "r"(a[0]), "r"(a[1]), "r"(a[2]), "r"(a[3]), "r"(b[0]), "r"(b[1]));
}
__device__ __forceinline__ void ldsm4(uint32_t addr, uint32_t* d) {
    asm volatile("ldmatrix.sync.aligned.m8n8.x4.shared.b16 {%0,%1,%2,%3}, [%4];"
        : "=r"(d[0]), "=r"(d[1]), "=r"(d[2]), "=r"(d[3]) : "r"(addr));
}
__device__ __forceinline__ void ldsm4t(uint32_t addr, uint32_t* d) {
    asm volatile("ldmatrix.sync.aligned.m8n8.x4.trans.shared.b16 {%0,%1,%2,%3}, [%4];"
        : "=r"(d[0]), "=r"(d[1]), "=r"(d[2]), "=r"(d[3]) : "r"(addr));
}
__device__ __forceinline__ uint32_t smem_u32(const void* p) {
    uint32_t a;
    asm("{ .reg .u64 t; cvta.to.shared.u64 t, %1; cvt.u32.u64 %0, t; }"
        : "=r"(a) : "l"(p));
    return a;
}
__device__ __forceinline__ void cp16(uint32_t dst, const void* src) {
    asm volatile("cp.async.cg.shared.global [%0], [%1], 16;"
                 :: "r"(dst), "l"(src) : "memory");
}
__device__ __forceinline__ void cp_commit() {
    asm volatile("cp.async.commit_group;" ::: "memory");
}
template<int N> __device__ __forceinline__ void cp_wait() {
    asm volatile("cp.async.wait_group %0;" :: "n"(N) : "memory");
}
__device__ __forceinline__ uint32_t h2pack(float a, float b) {
    __half2 h = __floats2half2_rn(a, b);
    return *(uint32_t*)&h;
}

// ---------------------------------------------------------------------------
// pre-convert: fp32 -> fp16 (rn), all three inputs in one launch
// ---------------------------------------------------------------------------
#define N4_X   (M_TOT*DD/4)
#define N4_WI  (3*DD*DD/4)
#define N4_WO  (DD*DD/4)
__global__ __launch_bounds__(256)
void roundcpy_all(const float4* __restrict__ x,  uint2* __restrict__ dx,
                  const float4* __restrict__ wi, uint2* __restrict__ dwi,
                  const float4* __restrict__ wo, uint2* __restrict__ dwo)
{
    int i = blockIdx.x * 256 + threadIdx.x;
    const float4* s;
    uint2* d;
    int off;
    if (i < N4_X)              { s = x;  d = dx;  off = i; }
    else if (i < N4_X + N4_WI) { s = wi; d = dwi; off = i - N4_X; }
    else                       { s = wo; d = dwo; off = i - N4_X - N4_WI; }
    float4 v = s[off];
    __half2 a = __floats2half2_rn(v.x, v.y);
    __half2 b = __floats2half2_rn(v.z, v.w);
    uint2 u;
    u.x = *(uint32_t*)&a;
    u.y = *(uint32_t*)&b;
    d[off] = u;
}

// ---------------------------------------------------------------------------
// fp16 mma.sync GEMM: 512 threads, 16 warps 4m x 4n (warp 32x32), 2 CTAs/SM,
// BK=64, 3-stage cp.async. CHANGE vs R14: prefetch of chunk c+2 is issued
// AFTER the mma block (stage (s+2)%3 = chunk c-1's stage, already released
// by the top-of-iter barrier), so mma starts immediately after the barrier.
// ---------------------------------------------------------------------------
__global__ __launch_bounds__(512, 2)
void gemm_tc(const __half* __restrict__ A, const __half* __restrict__ W,
             const float* __restrict__ bias, float* __restrict__ Cout, int mode)
{
    extern __shared__ __half smh[];
    const uint32_t sb = smem_u32(smh);

    const int tid  = threadIdx.x;
    const int wid  = tid >> 5;
    const int lane = tid & 31;
    const int gid  = lane >> 2;
    const int tig  = lane & 3;
    const int wm   = (wid >> 2) * 32;
    const int wn   = (wid & 3) * 32;
    const int m0   = blockIdx.y * BM;
    const int n0   = blockIdx.x * BN;

    const int ar = tid >> 2;
    const int ac = (tid & 3) * 16;
    const __half* gA = A + (size_t)(m0 + ar) * KK + ac;
    const __half* gB = W + (size_t)(n0 + ar) * KK + ac;
    const uint32_t sA_cp = sb + (uint32_t)(ar * PITH + ac) * 2;
    const uint32_t sB_cp = sb + (uint32_t)(A_STH + ar * PITH + ac) * 2;

    const uint32_t aoff = (uint32_t)((wm + (lane & 15)) * PITH + ((lane >> 1) & 8)) * 2;
    const uint32_t boff = (uint32_t)(A_STH + (wn + (lane & 7) + ((lane >> 1) & 8)) * PITH
                                     + (lane & 8)) * 2;

#define LOADCHUNK(c, s) do {                                        \
        uint32_t off_ = (uint32_t)(s) * (STGH * 2);                 \
        const __half* pa_ = gA + (c) * BKH;                         \
        const __half* pb_ = gB + (c) * BKH;                         \
        cp16(sA_cp + off_ +  0, pa_ + 0);                           \
        cp16(sA_cp + off_ + 16, pa_ + 8);                           \
        cp16(sB_cp + off_ +  0, pb_ + 0);                           \
        cp16(sB_cp + off_ + 16, pb_ + 8);                           \
    } while (0)

    LOADCHUNK(0, 0); cp_commit();
    LOADCHUNK(1, 1); cp_commit();

    float acc[2][4][4];
#pragma unroll
    for (int mi = 0; mi < 2; mi++)
#pragma unroll
        for (int ni = 0; ni < 4; ni++)
#pragma unroll
            for (int e = 0; e < 4; e++) acc[mi][ni][e] = 0.f;

    int s = 0;
    for (int c = 0; c < NCH; c++) {
        cp_wait<1>();
        __syncthreads();           // chunk c resident + chunk c-1 reads done

        const uint32_t stg = sb + (uint32_t)s * (STGH * 2);
#pragma unroll
        for (int kb = 0; kb < 4; kb++) {
            uint32_t af[2][4], bf[2][4];
#pragma unroll
            for (int mi = 0; mi < 2; mi++)
                ldsm4(stg + aoff + mi * (16 * PITH * 2) + kb * 32, af[mi]);
#pragma unroll
            for (int nj = 0; nj < 2; nj++)
                ldsm4(stg + boff + nj * (16 * PITH * 2) + kb * 32, bf[nj]);
#pragma unroll
            for (int njp = 0; njp < 2; njp++) {
#pragma unroll
                for (int mi = 0; mi < 2; mi++) {
                    mma_h(acc[mi][2 * njp],     af[mi], bf[njp]);
                    mma_h(acc[mi][2 * njp + 1], af[mi], bf[njp] + 2);
                }
            }
        }

        // prefetch AFTER mma: stage (s+2)%3 was released by this iter's barrier
        if (c + 2 < NCH) {
            int s2 = s + 2; if (s2 >= 3) s2 -= 3;
            LOADCHUNK(c + 2, s2);
        }
        cp_commit();
        if (++s == 3) s = 0;
    }
#undef LOADCHUNK

#pragma unroll
    for (int ni = 0; ni < 4; ni++) {
        const int n = n0 + wn + ni * 8 + 2 * tig;
        const float b0 = __ldg(bias + n);
        const float b1 = __ldg(bias + n + 1);

        if (mode == 0) {
            const int chunk = n >> 10;
            const int cm = n & 1023;
            const int h  = cm >> 6;
            const int dd = cm & 63;
            __half* dst = (chunk == 0) ? g_q : (chunk == 1) ? g_k : g_v;
#pragma unroll
            for (int mi = 0; mi < 2; mi++) {
                const int r0 = m0 + wm + mi * 16 + gid;
                const int bb0 = r0 >> 11, sr0 = r0 & 2047;
                const int r1 = r0 + 8;
                const int bb1 = r1 >> 11, sr1 = r1 & 2047;
                __half2 v0 = __floats2half2_rn(acc[mi][ni][0] + b0, acc[mi][ni][1] + b1);
                __half2 v1 = __floats2half2_rn(acc[mi][ni][2] + b0, acc[mi][ni][3] + b1);
                *(__half2*)(dst + ((size_t)(bb0 * HH + h) * SS + sr0) * DH + dd) = v0;
                *(__half2*)(dst + ((size_t)(bb1 * HH + h) * SS + sr1) * DH + dd) = v1;
            }
        } else {
#pragma unroll
            for (int mi = 0; mi < 2; mi++) {
                const int r0 = m0 + wm + mi * 16 + gid;
                const int r1 = r0 + 8;
                float2 v0 = make_float2(acc[mi][ni][0] + b0, acc[mi][ni][1] + b1);
                float2 v1 = make_float2(acc[mi][ni][2] + b0, acc[mi][ni][3] + b1);
                *(float2*)(Cout + (size_t)r0 * DD + n) = v0;
                *(float2*)(Cout + (size_t)r1 * DD + n) = v1;
            }
        }
    }
}

// ---------------------------------------------------------------------------
// fp16 flash attention (exact R14 version — 432.6us): register-P,
// 3-stage K/V, ONE __syncthreads per iteration, 2 CTAs/SM.
// smem (halfs): [Q 128x72 (prologue only)][K 3x64x72][V 3x64x72]
// ---------------------------------------------------------------------------
#define QP_H   9216
#define K_OFFH QP_H                    // 9216
#define KBUFH  4608                    // 64*72
#define V_OFFH (K_OFFH + 3*KBUFH)      // 23040
#define VBUFH  4608
#define ATT_SMEM ((V_OFFH + 3*VBUFH)*2)   // 73728 bytes

__global__ __launch_bounds__(256, 2)
void attn_tc()
{
    extern __shared__ __half smh[];

    const int tid  = threadIdx.x;
    const int wid  = tid >> 5;
    const int lane = tid & 31;
    const int g    = lane >> 2;
    const int tig  = lane & 3;
    const int wq   = wid * 16;
    const int q0   = blockIdx.x * 128;
    const int bh   = blockIdx.y;

    const __half* gq = g_q + (size_t)bh * SS * DH;
    const __half* gk = g_k + (size_t)bh * SS * DH;
    const __half* gv = g_v + (size_t)bh * SS * DH;

    const uint32_t sQ = smem_u32(smh);
    const uint32_t sK = sQ + K_OFFH * 2;
    const uint32_t sV = sQ + V_OFFH * 2;

    // ---- prologue: Q + KV tiles 0,1 ----
#pragma unroll
    for (int j = 0; j < 4; j++) {
        int ch = tid + j * 256;
        int r = ch >> 3, c = ch & 7;
        cp16(sQ + (uint32_t)(r * PITH + c * 8) * 2, gq + (size_t)(q0 + r) * DH + c * 8);
    }
#pragma unroll
    for (int j = 0; j < 2; j++) {
        int ch = tid + j * 256;
        int t = ch >> 3, c = ch & 7;
        cp16(sK + (uint32_t)(t * PITH + c * 8) * 2, gk + (size_t)t * DH + c * 8);
        cp16(sV + (uint32_t)(t * PITH + c * 8) * 2, gv + (size_t)t * DH + c * 8);
    }
    cp_commit();
#pragma unroll
    for (int j = 0; j < 2; j++) {
        int ch = tid + j * 256;
        int t = ch >> 3, c = ch & 7;
        cp16(sK + (uint32_t)(KBUFH + t * PITH + c * 8) * 2, gk + (size_t)(64 + t) * DH + c * 8);
        cp16(sV + (uint32_t)(VBUFH + t * PITH + c * 8) * 2, gv + (size_t)(64 + t) * DH + c * 8);
    }
    cp_commit();

    cp_wait<1>();
    __syncthreads();

    // ---- Q A-fragments (16 q rows, k16 x 4), loaded once ----
    const uint32_t q_ab = sQ + (uint32_t)((lane & 15) * PITH + ((lane >> 1) & 8)) * 2;
    uint32_t qa[4][4];
#pragma unroll
    for (int kb = 0; kb < 4; kb++)
        ldsm4(q_ab + (uint32_t)((wq * PITH + kb * 16) * 2), qa[kb]);

    const uint32_t k_bb = sK + (uint32_t)(((lane & 7) + ((lane >> 1) & 8)) * PITH + (lane & 8)) * 2;
    const uint32_t v_bb = sV + (uint32_t)((lane & 15) * PITH + ((lane >> 1) & 8)) * 2;

    float oacc[8][4];
#pragma unroll
    for (int nj = 0; nj < 8; nj++)
#pragma unroll
        for (int e = 0; e < 4; e++) oacc[nj][e] = 0.f;
    float lp[2] = {0.f, 0.f};

    const float CEXP = 0.18033688011112042f;   // log2(e)/8

    int s = 0;
    for (int i = 0; i < SS / 64; i++) {
        cp_wait<1>();
        __syncthreads();           // tile i visible to all warps

        // ---- QK^T: S[16 q x 64 t] per warp ----
        float p[8][4];
#pragma unroll
        for (int nj = 0; nj < 8; nj++)
#pragma unroll
            for (int e = 0; e < 4; e++) p[nj][e] = 0.f;

        const uint32_t kstage = k_bb + (uint32_t)(s * KBUFH) * 2;
#pragma unroll
        for (int kb = 0; kb < 4; kb++) {
#pragma unroll
            for (int njp = 0; njp < 4; njp++) {
                uint32_t bfr[4];
                ldsm4(kstage + (uint32_t)((njp * 16 * PITH + kb * 16) * 2), bfr);
                mma_h(p[2 * njp],     qa[kb], bfr);
                mma_h(p[2 * njp + 1], qa[kb], bfr + 2);
            }
        }

        // ---- softmax (no max subtraction), keep exp(p) in registers ----
#pragma unroll
        for (int nj = 0; nj < 8; nj++) {
            p[nj][0] = ex2(p[nj][0] * CEXP);
            p[nj][1] = ex2(p[nj][1] * CEXP);
            p[nj][2] = ex2(p[nj][2] * CEXP);
            p[nj][3] = ex2(p[nj][3] * CEXP);
            lp[0] += p[nj][0] + p[nj][1];
            lp[1] += p[nj][2] + p[nj][3];
        }

        // ---- P @ V: P A-frags packed directly from S C-frags ----
        const uint32_t vstage = v_bb + (uint32_t)(s * VBUFH) * 2;
#pragma unroll
        for (int kb = 0; kb < 4; kb++) {
            uint32_t pa[4];
            pa[0] = h2pack(p[2 * kb][0],     p[2 * kb][1]);
            pa[1] = h2pack(p[2 * kb][2],     p[2 * kb][3]);
            pa[2] = h2pack(p[2 * kb + 1][0], p[2 * kb + 1][1]);
            pa[3] = h2pack(p[2 * kb + 1][2], p[2 * kb + 1][3]);
#pragma unroll
            for (int njp = 0; njp < 4; njp++) {
                uint32_t vf[4];
                ldsm4t(vstage + (uint32_t)((kb * 16 * PITH + njp * 16) * 2), vf);
                mma_h(oacc[2 * njp],     pa, vf);
                mma_h(oacc[2 * njp + 1], pa, vf + 2);
            }
        }

        // ---- prefetch tile i+2 into stage (s+2)%3 (no barrier needed) ----
        if (i + 2 < SS / 64) {
            int sp = s + 2; if (sp >= 3) sp -= 3;
            const size_t t0 = (size_t)(i + 2) * 64;
#pragma unroll
            for (int j = 0; j < 2; j++) {
                int ch = tid + j * 256;
                int t = ch >> 3, c = ch & 7;
                cp16(sK + (uint32_t)(sp * KBUFH + t * PITH + c * 8) * 2,
                     gk + (t0 + t) * DH + c * 8);
                cp16(sV + (uint32_t)(sp * VBUFH + t * PITH + c * 8) * 2,
                     gv + (t0 + t) * DH + c * 8);
            }
        }
        cp_commit();
        if (++s == 3) s = 0;
    }

    // ---- normalize and write fp16 g_att [B,S,D] ----
    float ri[2];
#pragma unroll
    for (int hh = 0; hh < 2; hh++) {
        float l = lp[hh];
        l += __shfl_xor_sync(0xffffffffu, l, 1);
        l += __shfl_xor_sync(0xffffffffu, l, 2);
        ri[hh] = 1.f / l;
    }

    const int bb = bh >> 4;
    const int h  = bh & 15;
    const int r0 = q0 + wq + g;
    __half* base = g_att + ((size_t)bb * SS + r0) * DD + h * DH + 2 * tig;
#pragma unroll
    for (int nj = 0; nj < 8; nj++) {
        __half2 v0 = __floats2half2_rn(oacc[nj][0] * ri[0],
                                       oacc[nj][1] * ri[0]);
        __half2 v1 = __floats2half2_rn(oacc[nj][2] * ri[1],
                                       oacc[nj][3] * ri[1]);
        *(__half2*)(base + nj * 8) = v0;
        *(__half2*)(base + (size_t)8 * DD + nj * 8) = v1;
    }
}

// ---------------------------------------------------------------------------

extern "C" void kernel_launch(void* const* d_in, const int* in_sizes, int n_in,
                              void* d_out, int out_size)
{
    const float* x      = (const float*)d_in[0];
    const float* w_in   = (const float*)d_in[1];
    const float* b_in   = (const float*)d_in[2];
    const float* w_out  = (const float*)d_in[3];
    const float* b_out  = (const float*)d_in[4];
    float* out = (float*)d_out;

    (void)in_sizes; (void)n_in; (void)out_size;

    cudaFuncSetAttribute(gemm_tc, cudaFuncAttributeMaxDynamicSharedMemorySize,
                         GEMM_SMEM);
    cudaFuncSetAttribute(attn_tc, cudaFuncAttributeMaxDynamicSharedMemorySize,
                         ATT_SMEM);

    __half *xr, *wir, *wor, *attp;
    cudaGetSymbolAddress((void**)&xr,   g_xr);
    cudaGetSymbolAddress((void**)&wir,  g_wir);
    cudaGetSymbolAddress((void**)&wor,  g_wor);
    cudaGetSymbolAddress((void**)&attp, g_att);

    // 0) pre-convert all inputs to fp16 (single launch)
    roundcpy_all<<<(N4_X + N4_WI + N4_WO) / 256, 256>>>(
        (const float4*)x,     (uint2*)xr,
        (const float4*)w_in,  (uint2*)wir,
        (const float4*)w_out, (uint2*)wor);

    // 1) QKV projection (fp16 mma, 512 thr, 2 CTA/SM) + bias + head reshape
    gemm_tc<<<dim3(3 * DD / BN, M_TOT / BM), 512, GEMM_SMEM>>>(xr, wir, b_in, nullptr, 0);

    // 2) fp16 flash attention, register-P, 3-stage K/V, 1 barrier/iter
    attn_tc<<<dim3(SS / 128, BB * HH), 256, ATT_SMEM>>>();

    // 3) out projection (fp16 mma, 512 thr, 2 CTA/SM) + bias -> fp32 out
    gemm_tc<<<dim3(DD / BN, M_TOT / BM), 512, GEMM_SMEM>>>(attp, wor, b_out, out, 1);
}